// round 11
// baseline (speedup 1.0000x reference)
#include <cuda_runtime.h>
#include <cuda_bf16.h>
#include <cstdint>

// ---------------------------------------------------------------- constants
#define BB 16
#define CC_ 256
#define HWN 4096
#define EPSV 1e-5f
#define TOTAL (BB*CC_*HWN)   // 16,777,216

// ---------------------------------------------------------------- scratch
__device__ float g_q [TOTAL];
__device__ float g_k [TOTAL];
__device__ float g_v [TOTAL];
__device__ __nv_bfloat16 g_xnT_hi[TOTAL];
__device__ __nv_bfloat16 g_xnT_lo[TOTAL];
__device__ __nv_bfloat16 g_aoT_hi[TOTAL];
__device__ __nv_bfloat16 g_aoT_lo[TOTAL];
__device__ __nv_bfloat16 g_wqkv_hi[768*256];
__device__ __nv_bfloat16 g_wqkv_lo[768*256];
__device__ __nv_bfloat16 g_wproj_hi[256*256];
__device__ __nv_bfloat16 g_wproj_lo[256*256];
__device__ float g_mean[BB*8];
__device__ float g_rstd[BB*8];
__device__ float g_P[BB*64*16];     // softmax'd 4x4 per (b,e)

// ---------------------------------------------------------------- PTX helpers
__device__ __forceinline__ uint32_t smem_u32(const void* p) {
    uint32_t a;
    asm("{ .reg .u64 t; cvta.to.shared.u64 t, %1; cvt.u32.u64 %0, t; }" : "=r"(a) : "l"(p));
    return a;
}
__device__ __forceinline__ void ldsm4(uint32_t* r, uint32_t addr) {
    asm volatile("ldmatrix.sync.aligned.m8n8.x4.shared.b16 {%0,%1,%2,%3}, [%4];"
                 : "=r"(r[0]), "=r"(r[1]), "=r"(r[2]), "=r"(r[3]) : "r"(addr));
}
__device__ __forceinline__ void mma16816(float* d, const uint32_t* a, const uint32_t* b) {
    asm volatile("mma.sync.aligned.m16n8k16.row.col.f32.bf16.bf16.f32 "
                 "{%0,%1,%2,%3}, {%4,%5,%6,%7}, {%8,%9}, {%0,%1,%2,%3};"
                 : "+f"(d[0]), "+f"(d[1]), "+f"(d[2]), "+f"(d[3])
                 : "r"(a[0]), "r"(a[1]), "r"(a[2]), "r"(a[3]), "r"(b[0]), "r"(b[1]));
}
__device__ __forceinline__ void cpasync16(uint32_t dst, const void* src) {
    asm volatile("cp.async.cg.shared.global [%0], [%1], 16;" :: "r"(dst), "l"(src));
}
#define CP_COMMIT() asm volatile("cp.async.commit_group;" ::: "memory")
#define CP_WAIT(n)  asm volatile("cp.async.wait_group %0;" :: "n"(n) : "memory")

// 16B-unit swizzled offset inside an 8KB region: 128 rows x 4 units (64B row)
__device__ __forceinline__ uint32_t swz_unit(int row, int u) {
    return (uint32_t)((row*4 + (u ^ ((row >> 1) & 3))) * 16);
}

// ---------------------------------------------------------------- 1) GN stats
__global__ __launch_bounds__(256) void gn_stats_kernel(const float* __restrict__ x)
{
    const int bg  = blockIdx.x;
    const int tid = threadIdx.x;
    const float4* p4 = (const float4*)(x + (size_t)bg * 32 * HWN);
    float s = 0.f, s2 = 0.f;
    for (int i = tid; i < 32*HWN/4; i += 256) {
        float4 v = p4[i];
        s  += v.x + v.y + v.z + v.w;
        s2 += v.x*v.x + v.y*v.y + v.z*v.z + v.w*v.w;
    }
    __shared__ float rs[256], rs2[256];
    rs[tid] = s; rs2[tid] = s2;
    __syncthreads();
    for (int off = 128; off > 0; off >>= 1) {
        if (tid < off) { rs[tid] += rs[tid+off]; rs2[tid] += rs2[tid+off]; }
        __syncthreads();
    }
    if (tid == 0) {
        const float inv_n = 1.f / (float)(32*HWN);
        float mean = rs[0] * inv_n;
        float var  = rs2[0] * inv_n - mean*mean;
        g_mean[bg] = mean;
        g_rstd[bg] = rsqrtf(var + EPSV);
    }
}

// ------------------------------------------- 2) GN apply + transpose -> bf16 hi/lo [b][n][c]
__global__ __launch_bounds__(256) void gn_apply_t_kernel(const float* __restrict__ x,
                                                         const float* __restrict__ nw,
                                                         const float* __restrict__ nb)
{
    const int nt = blockIdx.x, ct = blockIdx.y, b = blockIdx.z;
    const int n0 = nt*32, c0 = ct*32;
    __shared__ float tile[32][33];
    const int col = threadIdx.x & 31, r = threadIdx.x >> 5;
    #pragma unroll
    for (int p = 0; p < 4; p++) {
        int cl = r + p*8;
        int c = c0 + cl;
        float rstd = g_rstd[b*8 + (c >> 5)];
        float mean = g_mean[b*8 + (c >> 5)];
        float sw = nw[c]*rstd, sb2 = nb[c] - mean*sw;
        float v = x[((size_t)(b*CC_+c))*HWN + n0 + col];
        tile[cl][col] = v*sw + sb2;
    }
    __syncthreads();
    #pragma unroll
    for (int p = 0; p < 4; p++) {
        int nl = r + p*8;
        float v = tile[col][nl];
        __nv_bfloat16 hi = __float2bfloat16(v);
        __nv_bfloat16 lo = __float2bfloat16(v - __bfloat162float(hi));
        size_t idx = ((size_t)(b*HWN + n0 + nl))*CC_ + c0 + col;
        g_xnT_hi[idx] = hi; g_xnT_lo[idx] = lo;
    }
}

// ---------------------------------------------------------------- 3) weight prep
__global__ __launch_bounds__(256) void wprep_kernel(const float* __restrict__ qkv_w,
                                                    const float* __restrict__ proj_w)
{
    const int i = blockIdx.x * 256 + threadIdx.x;
    if (i < 768*256) {
        float v = qkv_w[i];
        __nv_bfloat16 hi = __float2bfloat16(v);
        g_wqkv_hi[i] = hi;
        g_wqkv_lo[i] = __float2bfloat16(v - __bfloat162float(hi));
    }
    if (i < 256*256) {
        float v = proj_w[i];
        __nv_bfloat16 hi = __float2bfloat16(v);
        g_wproj_hi[i] = hi;
        g_wproj_lo[i] = __float2bfloat16(v - __bfloat162float(hi));
    }
}

// ---------------------------------------------------------------- HMMA GEMM
// D[m0+row, n0+col] = sum_c W[m0+row, c] * X[b, n0+col, c]   (K=256, 8 chunks of 32)
// CTA tile 128x128, 8 warps (2 along M x 4 along N), warp tile 64x32.
// 3 passes: Ahi*Bhi + Alo*Bhi + Ahi*Blo (ordered for register liveness).
// 3-stage cp.async pipeline, 2 CTAs/SM (96KB smem, <=128 regs).
// MODE 0: qkv -> q/k/v fp32 [b][c][n] (+bias). MODE 1: proj -> out = D + bias + x.
#define STAGE_BYTES 32768
#define NSTAGE 3
#define SMEM_TOTAL_MMA (STAGE_BYTES*NSTAGE)   // 98304

template<int MODE>
__global__ __launch_bounds__(256, 2) void hmma_gemm_kernel(const float* __restrict__ bias,
                                                           const float* __restrict__ xres,
                                                           float* __restrict__ out)
{
    extern __shared__ char smem[];
    const uint32_t sb = smem_u32(smem);
    const int tid = threadIdx.x;
    const int lane = tid & 31, wid = tid >> 5;
    const int wm = wid & 1, wn = wid >> 1;
    const int n0 = blockIdx.x * 128, m0 = blockIdx.y * 128, b = blockIdx.z;

    const __nv_bfloat16* __restrict__ Whi = (MODE == 0) ? g_wqkv_hi : g_wproj_hi;
    const __nv_bfloat16* __restrict__ Wlo = (MODE == 0) ? g_wqkv_lo : g_wproj_lo;
    const __nv_bfloat16* __restrict__ Xhi = (MODE == 0) ? g_xnT_hi  : g_aoT_hi;
    const __nv_bfloat16* __restrict__ Xlo = (MODE == 0) ? g_xnT_lo  : g_aoT_lo;

    float acc[4][4][4] = {};

    const int row_a = tid >> 2, u_a = tid & 3;

    auto load_chunk = [&](int chunk, int stage) {
        const int c0 = chunk * 32;
        const uint32_t base = sb + (uint32_t)stage * STAGE_BYTES;
        #pragma unroll
        for (int it = 0; it < 2; it++) {
            const int row = row_a + it*64;
            const uint32_t du = swz_unit(row, u_a);
            const size_t sa = (size_t)(m0 + row)*256 + c0 + u_a*8;
            cpasync16(base +         du, Whi + sa);
            cpasync16(base + 8192u + du, Wlo + sa);
            const size_t sx = (size_t)(b*HWN + n0 + row)*256 + c0 + u_a*8;
            cpasync16(base + 16384u + du, Xhi + sx);
            cpasync16(base + 24576u + du, Xlo + sx);
        }
        CP_COMMIT();
    };

    auto compute = [&](int stage) {
        const uint32_t base = sb + (uint32_t)stage * STAGE_BYTES;
        #pragma unroll
        for (int ks = 0; ks < 2; ks++) {
            uint32_t a0[4][4], a1[4][4], bb0[4][2], bb1[4][2];
            // A-hi + B-hi
            #pragma unroll
            for (int i = 0; i < 4; i++) {
                const int row = wm*64 + i*16 + (lane & 15);
                const int u   = ks*2 + (lane >> 4);
                ldsm4(a0[i], base + swz_unit(row, u));
            }
            #pragma unroll
            for (int jj = 0; jj < 2; jj++) {
                const int row = wn*32 + jj*16 + ((lane >> 4) & 1)*8 + (lane & 7);
                const int u   = ks*2 + ((lane >> 3) & 1);
                uint32_t r[4];
                ldsm4(r, base + 16384u + swz_unit(row, u));
                bb0[jj*2+0][0] = r[0]; bb0[jj*2+0][1] = r[1];
                bb0[jj*2+1][0] = r[2]; bb0[jj*2+1][1] = r[3];
            }
            #pragma unroll
            for (int i = 0; i < 4; i++)
                #pragma unroll
                for (int j = 0; j < 4; j++)
                    mma16816(acc[i][j], a0[i], bb0[j]);   // Ahi*Bhi
            // A-lo
            #pragma unroll
            for (int i = 0; i < 4; i++) {
                const int row = wm*64 + i*16 + (lane & 15);
                const int u   = ks*2 + (lane >> 4);
                ldsm4(a1[i], base + 8192u + swz_unit(row, u));
            }
            #pragma unroll
            for (int i = 0; i < 4; i++)
                #pragma unroll
                for (int j = 0; j < 4; j++)
                    mma16816(acc[i][j], a1[i], bb0[j]);   // Alo*Bhi
            // B-lo (a1 dead from here; bb1 can reuse its registers)
            #pragma unroll
            for (int jj = 0; jj < 2; jj++) {
                const int row = wn*32 + jj*16 + ((lane >> 4) & 1)*8 + (lane & 7);
                const int u   = ks*2 + ((lane >> 3) & 1);
                uint32_t r[4];
                ldsm4(r, base + 24576u + swz_unit(row, u));
                bb1[jj*2+0][0] = r[0]; bb1[jj*2+0][1] = r[1];
                bb1[jj*2+1][0] = r[2]; bb1[jj*2+1][1] = r[3];
            }
            #pragma unroll
            for (int i = 0; i < 4; i++)
                #pragma unroll
                for (int j = 0; j < 4; j++)
                    mma16816(acc[i][j], a0[i], bb1[j]);   // Ahi*Blo
        }
    };

    // prefetch 2 chunks
    load_chunk(0, 0);
    load_chunk(1, 1);

    #pragma unroll
    for (int c = 0; c < 8; c++) {
        if (c < 7) CP_WAIT(1);
        else CP_WAIT(0);
        __syncthreads();
        // stage (c+2)%3 was consumed at iter c-1 -> safe to refill after this barrier
        if (c + 2 < 8) load_chunk(c + 2, (c + 2) % 3);
        compute(c % 3);
    }

    // ---------------- epilogue ----------------
    #pragma unroll
    for (int i = 0; i < 4; i++) {
        const int row0 = m0 + wm*64 + i*16 + (lane >> 2);
        #pragma unroll
        for (int half = 0; half < 2; half++) {
            const int o = row0 + half*8;
            const float bv = bias[o];
            float* dst;
            const float* xr = nullptr;
            if (MODE == 0) {
                const int part = o >> 8, co = o & 255;
                float* basep = (part == 0) ? g_q : (part == 1) ? g_k : g_v;
                dst = basep + ((size_t)(b*CC_ + co))*HWN + n0;
            } else {
                const size_t off = ((size_t)(b*CC_ + o))*HWN + n0;
                dst = out + off;
                xr  = xres + off;
            }
            #pragma unroll
            for (int j = 0; j < 4; j++) {
                const int col = wn*32 + j*8 + (lane & 3)*2;
                float2 t;
                t.x = acc[i][j][half*2+0] + bv;
                t.y = acc[i][j][half*2+1] + bv;
                if (MODE == 1) { t.x += xr[col]; t.y += xr[col+1]; }
                *(float2*)(dst + col) = t;
            }
        }
    }
}

// ---------------------------------------------------------------- 4) gram + softmax -> g_P
__global__ __launch_bounds__(256) void gram_kernel()
{
    const int be = blockIdx.x;           // b*64 + e
    const int b  = be >> 6;
    const int e  = be & 63;
    const int tid = threadIdx.x;

    const size_t base = (size_t)(b*CC_ + e) * HWN;
    const float4* qp = (const float4*)(g_q + base);
    const float4* kp = (const float4*)(g_k + base);

    float acc[16] = {};
    for (int s = tid; s < HWN/4; s += 256) {
        float4 qv[4], kv[4];
        #pragma unroll
        for (int i = 0; i < 4; i++) qv[i] = qp[(size_t)i*16*HWN + s];   // 64*HWN/4
        #pragma unroll
        for (int j = 0; j < 4; j++) kv[j] = kp[(size_t)j*16*HWN + s];
        #pragma unroll
        for (int i = 0; i < 4; i++)
            #pragma unroll
            for (int j = 0; j < 4; j++)
                acc[i*4+j] += qv[i].x*kv[j].x + qv[i].y*kv[j].y
                            + qv[i].z*kv[j].z + qv[i].w*kv[j].w;
    }

    __shared__ float red[16][264];
    #pragma unroll
    for (int v = 0; v < 16; v++) red[v][tid] = acc[v];
    __syncthreads();

    if (tid < 16) {
        float s = 0.f;
        for (int t = 0; t < 256; t++) s += red[tid][t];
        red[tid][256] = s * 0.125f;     // scale = dh^-0.5
    }
    __syncthreads();
    if (tid < 4) {
        float g0 = red[tid*4+0][256], g1 = red[tid*4+1][256];
        float g2 = red[tid*4+2][256], g3 = red[tid*4+3][256];
        float m = fmaxf(fmaxf(g0, g1), fmaxf(g2, g3));
        float e0 = expf(g0-m), e1 = expf(g1-m), e2 = expf(g2-m), e3 = expf(g3-m);
        float inv = 1.f / (e0+e1+e2+e3);
        float* P = g_P + be*16 + tid*4;
        P[0] = e0*inv; P[1] = e1*inv; P[2] = e2*inv; P[3] = e3*inv;
    }
}

// ------------------- 5) blend (P·v) + transpose + bf16 split -> aoT hi/lo [b][n][c]
__global__ __launch_bounds__(256) void blend_t_kernel()
{
    const int nt = blockIdx.x, et = blockIdx.y, b = blockIdx.z;
    const int n0 = nt*32, e0 = et*32;
    __shared__ float vt[4][32][33];

    const int col = threadIdx.x & 31, r = threadIdx.x >> 5;

    // load 4 v channel-tiles: channels j*64 + e0 + ch, n = n0 + col
    #pragma unroll
    for (int j = 0; j < 4; j++)
        #pragma unroll
        for (int p = 0; p < 4; p++) {
            const int ch = r + p*8;
            vt[j][ch][col] = g_v[((size_t)(b*CC_ + j*64 + e0 + ch))*HWN + n0 + col];
        }
    __syncthreads();

    // per-thread P row for e = e0 + col (col acts as ec in write phase)
    const int ec = col;
    float p[4][4];
    {
        const float* Pp = g_P + ((size_t)(b*64 + e0 + ec))*16;
        #pragma unroll
        for (int i = 0; i < 4; i++)
            #pragma unroll
            for (int j = 0; j < 4; j++) p[i][j] = Pp[i*4+j];
    }

    #pragma unroll
    for (int i = 0; i < 4; i++)
        #pragma unroll
        for (int pr = 0; pr < 4; pr++) {
            const int nr = r + pr*8;
            float v = p[i][0]*vt[0][ec][nr] + p[i][1]*vt[1][ec][nr]
                    + p[i][2]*vt[2][ec][nr] + p[i][3]*vt[3][ec][nr];
            __nv_bfloat16 hi = __float2bfloat16(v);
            __nv_bfloat16 lo = __float2bfloat16(v - __bfloat162float(hi));
            const size_t idx = ((size_t)(b*HWN + n0 + nr))*CC_ + i*64 + e0 + ec;
            g_aoT_hi[idx] = hi; g_aoT_lo[idx] = lo;
        }
}

// ---------------------------------------------------------------- launch
extern "C" void kernel_launch(void* const* d_in, const int* in_sizes, int n_in,
                              void* d_out, int out_size)
{
    const float* x      = (const float*)d_in[0];
    const float* norm_w = (const float*)d_in[1];
    const float* norm_b = (const float*)d_in[2];
    const float* qkv_w  = (const float*)d_in[3];
    const float* qkv_b  = (const float*)d_in[4];
    const float* proj_w = (const float*)d_in[5];
    const float* proj_b = (const float*)d_in[6];
    float* out = (float*)d_out;

    static bool attr_set = false;
    if (!attr_set) {
        cudaFuncSetAttribute(hmma_gemm_kernel<0>,
                             cudaFuncAttributeMaxDynamicSharedMemorySize, SMEM_TOTAL_MMA);
        cudaFuncSetAttribute(hmma_gemm_kernel<1>,
                             cudaFuncAttributeMaxDynamicSharedMemorySize, SMEM_TOTAL_MMA);
        attr_set = true;
    }

    gn_stats_kernel<<<BB*8, 256>>>(x);
    wprep_kernel<<<768, 256>>>(qkv_w, proj_w);
    gn_apply_t_kernel<<<dim3(128, 8, BB), 256>>>(x, norm_w, norm_b);
    hmma_gemm_kernel<0><<<dim3(32, 6, BB), 256, SMEM_TOTAL_MMA>>>(qkv_b, nullptr, nullptr);
    gram_kernel<<<BB*64, 256>>>();
    blend_t_kernel<<<dim3(128, 2, BB), 256>>>();
    hmma_gemm_kernel<1><<<dim3(32, 2, BB), 256, SMEM_TOTAL_MMA>>>(proj_b, x, out);
}

// round 12
// speedup vs baseline: 1.0626x; 1.0626x over previous
#include <cuda_runtime.h>
#include <cuda_bf16.h>
#include <cstdint>

// ---------------------------------------------------------------- constants
#define BB 16
#define CC_ 256
#define HWN 4096
#define EPSV 1e-5f
#define TOTAL (BB*CC_*HWN)   // 16,777,216

// ---------------------------------------------------------------- scratch
__device__ float g_q [TOTAL];
__device__ float g_k [TOTAL];
__device__ __nv_bfloat16 g_xnT_hi[TOTAL];
__device__ __nv_bfloat16 g_xnT_lo[TOTAL];
__device__ __nv_bfloat16 g_vT_hi[TOTAL];
__device__ __nv_bfloat16 g_vT_lo[TOTAL];
__device__ __nv_bfloat16 g_wqkv_hi[768*256];
__device__ __nv_bfloat16 g_wqkv_lo[768*256];
__device__ __nv_bfloat16 g_wt_hi[BB*256*256];   // per-batch folded proj weights
__device__ __nv_bfloat16 g_wt_lo[BB*256*256];
__device__ float g_mean[BB*8];
__device__ float g_rstd[BB*8];
__device__ float g_P[BB*64*16];     // softmax'd 4x4 per (b,e)

// ---------------------------------------------------------------- PTX helpers
__device__ __forceinline__ uint32_t smem_u32(const void* p) {
    uint32_t a;
    asm("{ .reg .u64 t; cvta.to.shared.u64 t, %1; cvt.u32.u64 %0, t; }" : "=r"(a) : "l"(p));
    return a;
}
__device__ __forceinline__ void ldsm4(uint32_t* r, uint32_t addr) {
    asm volatile("ldmatrix.sync.aligned.m8n8.x4.shared.b16 {%0,%1,%2,%3}, [%4];"
                 : "=r"(r[0]), "=r"(r[1]), "=r"(r[2]), "=r"(r[3]) : "r"(addr));
}
__device__ __forceinline__ void mma16816(float* d, const uint32_t* a, const uint32_t* b) {
    asm volatile("mma.sync.aligned.m16n8k16.row.col.f32.bf16.bf16.f32 "
                 "{%0,%1,%2,%3}, {%4,%5,%6,%7}, {%8,%9}, {%0,%1,%2,%3};"
                 : "+f"(d[0]), "+f"(d[1]), "+f"(d[2]), "+f"(d[3])
                 : "r"(a[0]), "r"(a[1]), "r"(a[2]), "r"(a[3]), "r"(b[0]), "r"(b[1]));
}
__device__ __forceinline__ void cpasync16(uint32_t dst, const void* src) {
    asm volatile("cp.async.cg.shared.global [%0], [%1], 16;" :: "r"(dst), "l"(src));
}
#define CP_COMMIT() asm volatile("cp.async.commit_group;" ::: "memory")
#define CP_WAIT(n)  asm volatile("cp.async.wait_group %0;" :: "n"(n) : "memory")

// 16B-unit swizzled offset inside an 8KB region: 128 rows x 4 units (64B row)
__device__ __forceinline__ uint32_t swz_unit(int row, int u) {
    return (uint32_t)((row*4 + (u ^ ((row >> 1) & 3))) * 16);
}

// ---------------------------------------------------------------- 1) GN stats
__global__ __launch_bounds__(256) void gn_stats_kernel(const float* __restrict__ x)
{
    const int bg  = blockIdx.x;
    const int tid = threadIdx.x;
    const float4* p4 = (const float4*)(x + (size_t)bg * 32 * HWN);
    float s = 0.f, s2 = 0.f;
    for (int i = tid; i < 32*HWN/4; i += 256) {
        float4 v = p4[i];
        s  += v.x + v.y + v.z + v.w;
        s2 += v.x*v.x + v.y*v.y + v.z*v.z + v.w*v.w;
    }
    __shared__ float rs[256], rs2[256];
    rs[tid] = s; rs2[tid] = s2;
    __syncthreads();
    for (int off = 128; off > 0; off >>= 1) {
        if (tid < off) { rs[tid] += rs[tid+off]; rs2[tid] += rs2[tid+off]; }
        __syncthreads();
    }
    if (tid == 0) {
        const float inv_n = 1.f / (float)(32*HWN);
        float mean = rs[0] * inv_n;
        float var  = rs2[0] * inv_n - mean*mean;
        g_mean[bg] = mean;
        g_rstd[bg] = rsqrtf(var + EPSV);
    }
}

// ------------------------------------------- 2) GN apply + transpose -> bf16 hi/lo [b][n][c]
__global__ __launch_bounds__(256) void gn_apply_t_kernel(const float* __restrict__ x,
                                                         const float* __restrict__ nw,
                                                         const float* __restrict__ nb)
{
    const int nt = blockIdx.x, ct = blockIdx.y, b = blockIdx.z;
    const int n0 = nt*32, c0 = ct*32;
    __shared__ float tile[32][33];
    const int col = threadIdx.x & 31, r = threadIdx.x >> 5;
    #pragma unroll
    for (int p = 0; p < 4; p++) {
        int cl = r + p*8;
        int c = c0 + cl;
        float rstd = g_rstd[b*8 + (c >> 5)];
        float mean = g_mean[b*8 + (c >> 5)];
        float sw = nw[c]*rstd, sb2 = nb[c] - mean*sw;
        float v = x[((size_t)(b*CC_+c))*HWN + n0 + col];
        tile[cl][col] = v*sw + sb2;
    }
    __syncthreads();
    #pragma unroll
    for (int p = 0; p < 4; p++) {
        int nl = r + p*8;
        float v = tile[col][nl];
        __nv_bfloat16 hi = __float2bfloat16(v);
        __nv_bfloat16 lo = __float2bfloat16(v - __bfloat162float(hi));
        size_t idx = ((size_t)(b*HWN + n0 + nl))*CC_ + c0 + col;
        g_xnT_hi[idx] = hi; g_xnT_lo[idx] = lo;
    }
}

// ---------------------------------------------------------------- 3) qkv weight prep
__global__ __launch_bounds__(256) void wprep_kernel(const float* __restrict__ qkv_w)
{
    const int i = blockIdx.x * 256 + threadIdx.x;
    if (i < 768*256) {
        float v = qkv_w[i];
        __nv_bfloat16 hi = __float2bfloat16(v);
        g_wqkv_hi[i] = hi;
        g_wqkv_lo[i] = __float2bfloat16(v - __bfloat162float(hi));
    }
}

// ---------------------------------------------------------------- HMMA GEMM
// D[m0+row, n0+col] = sum_c W[m0+row, c] * X[b, n0+col, c]   (K=256, 8 chunks of 32)
// CTA tile 128x128, 8 warps (2 along M x 4 along N), warp tile 64x32.
// 3 passes: Ahi*Bhi + Alo*Bhi + Ahi*Blo. 3-stage cp.async pipeline, 2 CTAs/SM.
// MODE 0: qkv. m-tiles 0..3 -> q/k fp32 [b][c][n] (+bias);
//              m-tiles 4,5 -> v, transposed in-epilogue to vT bf16 hi/lo [b][n][c].
// MODE 1: proj with per-batch folded weights W~: out = D + bias + x (residual).
#define STAGE_BYTES 32768
#define NSTAGE 3
#define SMEM_TOTAL_MMA (STAGE_BYTES*NSTAGE)   // 98304

template<int MODE>
__global__ __launch_bounds__(256, 2) void hmma_gemm_kernel(const float* __restrict__ bias,
                                                           const float* __restrict__ xres,
                                                           float* __restrict__ out)
{
    extern __shared__ char smem[];
    const uint32_t sb = smem_u32(smem);
    const int tid = threadIdx.x;
    const int lane = tid & 31, wid = tid >> 5;
    const int wm = wid & 1, wn = wid >> 1;
    const int n0 = blockIdx.x * 128, mt = blockIdx.y, b = blockIdx.z;
    const int m0 = mt * 128;

    const __nv_bfloat16* __restrict__ Whi =
        (MODE == 0) ? g_wqkv_hi : (g_wt_hi + (size_t)b * 65536);
    const __nv_bfloat16* __restrict__ Wlo =
        (MODE == 0) ? g_wqkv_lo : (g_wt_lo + (size_t)b * 65536);
    const __nv_bfloat16* __restrict__ Xhi = (MODE == 0) ? g_xnT_hi : g_vT_hi;
    const __nv_bfloat16* __restrict__ Xlo = (MODE == 0) ? g_xnT_lo : g_vT_lo;

    float acc[4][4][4] = {};

    const int row_a = tid >> 2, u_a = tid & 3;

    auto load_chunk = [&](int chunk, int stage) {
        const int c0 = chunk * 32;
        const uint32_t base = sb + (uint32_t)stage * STAGE_BYTES;
        #pragma unroll
        for (int it = 0; it < 2; it++) {
            const int row = row_a + it*64;
            const uint32_t du = swz_unit(row, u_a);
            const size_t sa = (size_t)(m0 + row)*256 + c0 + u_a*8;
            cpasync16(base +         du, Whi + sa);
            cpasync16(base + 8192u + du, Wlo + sa);
            const size_t sx = (size_t)(b*HWN + n0 + row)*256 + c0 + u_a*8;
            cpasync16(base + 16384u + du, Xhi + sx);
            cpasync16(base + 24576u + du, Xlo + sx);
        }
        CP_COMMIT();
    };

    auto compute = [&](int stage) {
        const uint32_t base = sb + (uint32_t)stage * STAGE_BYTES;
        #pragma unroll
        for (int ks = 0; ks < 2; ks++) {
            uint32_t a0[4][4], a1[4][4], bb0[4][2], bb1[4][2];
            #pragma unroll
            for (int i = 0; i < 4; i++) {
                const int row = wm*64 + i*16 + (lane & 15);
                const int u   = ks*2 + (lane >> 4);
                ldsm4(a0[i], base + swz_unit(row, u));
            }
            #pragma unroll
            for (int jj = 0; jj < 2; jj++) {
                const int row = wn*32 + jj*16 + ((lane >> 4) & 1)*8 + (lane & 7);
                const int u   = ks*2 + ((lane >> 3) & 1);
                uint32_t r[4];
                ldsm4(r, base + 16384u + swz_unit(row, u));
                bb0[jj*2+0][0] = r[0]; bb0[jj*2+0][1] = r[1];
                bb0[jj*2+1][0] = r[2]; bb0[jj*2+1][1] = r[3];
            }
            #pragma unroll
            for (int i = 0; i < 4; i++)
                #pragma unroll
                for (int j = 0; j < 4; j++)
                    mma16816(acc[i][j], a0[i], bb0[j]);   // Ahi*Bhi
            #pragma unroll
            for (int i = 0; i < 4; i++) {
                const int row = wm*64 + i*16 + (lane & 15);
                const int u   = ks*2 + (lane >> 4);
                ldsm4(a1[i], base + 8192u + swz_unit(row, u));
            }
            #pragma unroll
            for (int i = 0; i < 4; i++)
                #pragma unroll
                for (int j = 0; j < 4; j++)
                    mma16816(acc[i][j], a1[i], bb0[j]);   // Alo*Bhi
            #pragma unroll
            for (int jj = 0; jj < 2; jj++) {
                const int row = wn*32 + jj*16 + ((lane >> 4) & 1)*8 + (lane & 7);
                const int u   = ks*2 + ((lane >> 3) & 1);
                uint32_t r[4];
                ldsm4(r, base + 24576u + swz_unit(row, u));
                bb1[jj*2+0][0] = r[0]; bb1[jj*2+0][1] = r[1];
                bb1[jj*2+1][0] = r[2]; bb1[jj*2+1][1] = r[3];
            }
            #pragma unroll
            for (int i = 0; i < 4; i++)
                #pragma unroll
                for (int j = 0; j < 4; j++)
                    mma16816(acc[i][j], a0[i], bb1[j]);   // Ahi*Blo
        }
    };

    load_chunk(0, 0);
    load_chunk(1, 1);

    #pragma unroll
    for (int c = 0; c < 8; c++) {
        if (c < 7) CP_WAIT(1);
        else CP_WAIT(0);
        __syncthreads();
        if (c + 2 < 8) load_chunk(c + 2, (c + 2) % 3);
        compute(c % 3);
    }

    // ---------------- epilogue ----------------
    if (MODE == 0 && mt >= 4) {
        // v tiles: transpose via smem, write vT bf16 hi/lo [b][n][c]
        __syncthreads();
        float (*st)[130] = (float(*)[130])smem;   // [c_local][n_local]
        #pragma unroll
        for (int i = 0; i < 4; i++) {
            #pragma unroll
            for (int half = 0; half < 2; half++) {
                const int r2 = wm*64 + i*16 + (lane >> 2) + half*8;
                const float bv = bias[m0 + r2];
                #pragma unroll
                for (int j = 0; j < 4; j++) {
                    const int cl = wn*32 + j*8 + (lane & 3)*2;
                    st[r2][cl]   = acc[i][j][half*2+0] + bv;
                    st[r2][cl+1] = acc[i][j][half*2+1] + bv;
                }
            }
        }
        __syncthreads();
        const int n_l = tid >> 1;
        const int ch  = (tid & 1) * 64;
        const size_t gbase = ((size_t)(b*HWN + n0 + n_l))*CC_ + (mt - 4)*128 + ch;
        #pragma unroll
        for (int cc = 0; cc < 64; cc += 8) {
            uint32_t h[4], l[4];
            #pragma unroll
            for (int k2 = 0; k2 < 4; k2++) {
                float v0 = st[ch + cc + k2*2 + 0][n_l];
                float v1 = st[ch + cc + k2*2 + 1][n_l];
                __nv_bfloat16 h0 = __float2bfloat16(v0);
                __nv_bfloat16 h1 = __float2bfloat16(v1);
                __nv_bfloat16 l0 = __float2bfloat16(v0 - __bfloat162float(h0));
                __nv_bfloat16 l1 = __float2bfloat16(v1 - __bfloat162float(h1));
                h[k2] = (uint32_t)*(uint16_t*)&h0 | ((uint32_t)*(uint16_t*)&h1 << 16);
                l[k2] = (uint32_t)*(uint16_t*)&l0 | ((uint32_t)*(uint16_t*)&l1 << 16);
            }
            *(uint4*)(g_vT_hi + gbase + cc) = *(uint4*)h;
            *(uint4*)(g_vT_lo + gbase + cc) = *(uint4*)l;
        }
    } else {
        #pragma unroll
        for (int i = 0; i < 4; i++) {
            const int row0 = m0 + wm*64 + i*16 + (lane >> 2);
            #pragma unroll
            for (int half = 0; half < 2; half++) {
                const int o = row0 + half*8;
                const float bv = bias[o];
                float* dst;
                const float* xr = nullptr;
                if (MODE == 0) {
                    const int part = o >> 8, co = o & 255;   // part 0=q, 1=k
                    float* basep = (part == 0) ? g_q : g_k;
                    dst = basep + ((size_t)(b*CC_ + co))*HWN + n0;
                } else {
                    const size_t off = ((size_t)(b*CC_ + o))*HWN + n0;
                    dst = out + off;
                    xr  = xres + off;
                }
                #pragma unroll
                for (int j = 0; j < 4; j++) {
                    const int col = wn*32 + j*8 + (lane & 3)*2;
                    float2 t;
                    t.x = acc[i][j][half*2+0] + bv;
                    t.y = acc[i][j][half*2+1] + bv;
                    if (MODE == 1) { t.x += xr[col]; t.y += xr[col+1]; }
                    *(float2*)(dst + col) = t;
                }
            }
        }
    }
}

// ---------------------------------------------------------------- 4) gram + softmax -> g_P
__global__ __launch_bounds__(256) void gram_kernel()
{
    const int be = blockIdx.x;           // b*64 + e
    const int b  = be >> 6;
    const int e  = be & 63;
    const int tid = threadIdx.x;

    const size_t base = (size_t)(b*CC_ + e) * HWN;
    const float4* qp = (const float4*)(g_q + base);
    const float4* kp = (const float4*)(g_k + base);

    float acc[16] = {};
    for (int s = tid; s < HWN/4; s += 256) {
        float4 qv[4], kv[4];
        #pragma unroll
        for (int i = 0; i < 4; i++) qv[i] = qp[(size_t)i*16*HWN + s];   // 64*HWN/4
        #pragma unroll
        for (int j = 0; j < 4; j++) kv[j] = kp[(size_t)j*16*HWN + s];
        #pragma unroll
        for (int i = 0; i < 4; i++)
            #pragma unroll
            for (int j = 0; j < 4; j++)
                acc[i*4+j] += qv[i].x*kv[j].x + qv[i].y*kv[j].y
                            + qv[i].z*kv[j].z + qv[i].w*kv[j].w;
    }

    __shared__ float red[16][264];
    #pragma unroll
    for (int v = 0; v < 16; v++) red[v][tid] = acc[v];
    __syncthreads();

    if (tid < 16) {
        float s = 0.f;
        for (int t = 0; t < 256; t++) s += red[tid][t];
        red[tid][256] = s * 0.125f;     // scale = dh^-0.5
    }
    __syncthreads();
    if (tid < 4) {
        float g0 = red[tid*4+0][256], g1 = red[tid*4+1][256];
        float g2 = red[tid*4+2][256], g3 = red[tid*4+3][256];
        float m = fmaxf(fmaxf(g0, g1), fmaxf(g2, g3));
        float e0 = expf(g0-m), e1 = expf(g1-m), e2 = expf(g2-m), e3 = expf(g3-m);
        float inv = 1.f / (e0+e1+e2+e3);
        float* P = g_P + be*16 + tid*4;
        P[0] = e0*inv; P[1] = e1*inv; P[2] = e2*inv; P[3] = e3*inv;
    }
}

// ------------------- 5) fold proj_w with P -> per-batch W~ (bf16 hi/lo)
// W~[b][o][j*64+e] = sum_i proj_w[o, i*64+e] * P[b,e,i,j]
__global__ __launch_bounds__(256) void wt_prep_kernel(const float* __restrict__ proj_w)
{
    const int o = blockIdx.x;          // 0..255
    const int b = blockIdx.y;          // 0..15
    const int c = threadIdx.x;         // 0..255
    const int e = c & 63, j = c >> 6;
    const float* P = g_P + ((size_t)(b*64 + e))*16 + j;
    float s = 0.f;
    #pragma unroll
    for (int i = 0; i < 4; i++)
        s += proj_w[o*CC_ + i*64 + e] * P[i*4];
    __nv_bfloat16 hi = __float2bfloat16(s);
    __nv_bfloat16 lo = __float2bfloat16(s - __bfloat162float(hi));
    const size_t idx = ((size_t)b*CC_ + o)*CC_ + c;
    g_wt_hi[idx] = hi; g_wt_lo[idx] = lo;
}

// ---------------------------------------------------------------- launch
extern "C" void kernel_launch(void* const* d_in, const int* in_sizes, int n_in,
                              void* d_out, int out_size)
{
    const float* x      = (const float*)d_in[0];
    const float* norm_w = (const float*)d_in[1];
    const float* norm_b = (const float*)d_in[2];
    const float* qkv_w  = (const float*)d_in[3];
    const float* qkv_b  = (const float*)d_in[4];
    const float* proj_w = (const float*)d_in[5];
    const float* proj_b = (const float*)d_in[6];
    float* out = (float*)d_out;

    static bool attr_set = false;
    if (!attr_set) {
        cudaFuncSetAttribute(hmma_gemm_kernel<0>,
                             cudaFuncAttributeMaxDynamicSharedMemorySize, SMEM_TOTAL_MMA);
        cudaFuncSetAttribute(hmma_gemm_kernel<1>,
                             cudaFuncAttributeMaxDynamicSharedMemorySize, SMEM_TOTAL_MMA);
        attr_set = true;
    }

    gn_stats_kernel<<<BB*8, 256>>>(x);
    wprep_kernel<<<768, 256>>>(qkv_w);
    gn_apply_t_kernel<<<dim3(128, 8, BB), 256>>>(x, norm_w, norm_b);
    hmma_gemm_kernel<0><<<dim3(32, 6, BB), 256, SMEM_TOTAL_MMA>>>(qkv_b, nullptr, nullptr);
    gram_kernel<<<BB*64, 256>>>();
    wt_prep_kernel<<<dim3(CC_, BB), 256>>>(proj_w);
    hmma_gemm_kernel<1><<<dim3(32, 2, BB), 256, SMEM_TOTAL_MMA>>>(proj_b, x, out);
}